// round 6
// baseline (speedup 1.0000x reference)
#include <cuda_runtime.h>
#include <math.h>

#define EPSLN 1e-5f

// ---------------- device scratch (no allocations allowed) ----------------
__device__ float g_qwT[128 * 128];      // q_w transposed  [in][out]
__device__ float g_kwT[128 * 128];      // k_w transposed
__device__ float g_outwT[64 * 128];     // out_w transposed [64][128]
__device__ float g_wihT[128 * 384];     // gru_wih transposed [128][384]
__device__ float g_c1T[128 * 128];
__device__ float g_c2T[128 * 128];
__device__ float g_q[128 * 128];        // q rows (NT, E)
__device__ float g_kT[8 * 128 * 512];   // k transposed (B, E, T)
__device__ float g_att[8 * 128 * 64];   // attention output (B, NT, 2F)
__device__ float g_gi[128 * 8 * 384];   // GRU input gates (t, b, 3H)
__device__ float g_h[8 * 128];          // final hidden

// ---------------- fused weight transpose ----------------
__global__ void tr_all_kernel(const float* __restrict__ qw, const float* __restrict__ kw,
                              const float* __restrict__ ow, const float* __restrict__ wih,
                              const float* __restrict__ c1, const float* __restrict__ c2) {
    int idx = blockIdx.x * 256 + threadIdx.x;
    if (idx < 16384) { g_qwT[(idx & 127) * 128 + (idx >> 7)] = qw[idx]; return; }
    idx -= 16384;
    if (idx < 16384) { g_kwT[(idx & 127) * 128 + (idx >> 7)] = kw[idx]; return; }
    idx -= 16384;
    if (idx < 8192)  { int r = idx >> 6, c = idx & 63; g_outwT[c * 128 + r] = ow[idx]; return; }
    idx -= 8192;
    if (idx < 49152) { int r = idx >> 7, c = idx & 127; g_wihT[c * 384 + r] = wih[idx]; return; }
    idx -= 49152;
    if (idx < 16384) { g_c1T[(idx & 127) * 128 + (idx >> 7)] = c1[idx]; return; }
    idx -= 16384;
    if (idx < 16384) { g_c2T[(idx & 127) * 128 + (idx >> 7)] = c2[idx]; return; }
}

// ---------------- helpers ----------------
__device__ __forceinline__ float block_sum_128(float v, float* red) {
    #pragma unroll
    for (int o = 16; o > 0; o >>= 1) v += __shfl_down_sync(0xffffffffu, v, o);
    if ((threadIdx.x & 31) == 0) red[threadIdx.x >> 5] = v;
    __syncthreads();
    v = red[0] + red[1] + red[2] + red[3];
    __syncthreads();
    return v;
}

// ---------------- time embedding + projection + LN (q and k fused) ----------------
// blockIdx.x <  128 : query path, t = i/127, writes g_q row-major
// blockIdx.x >= 128 : key path, (b*512+t) = blockIdx.x-128, writes g_kT transposed
__global__ __launch_bounds__(128) void proj_kernel(
    const float* __restrict__ timesteps,
    const float* __restrict__ lin_w, const float* __restrict__ lin_b,
    const float* __restrict__ per_w, const float* __restrict__ per_b,
    const float* __restrict__ q_b, const float* __restrict__ q_g,
    const float* __restrict__ q_be,
    const float* __restrict__ k_b, const float* __restrict__ k_g,
    const float* __restrict__ k_be) {
    __shared__ float emb[128];
    __shared__ float red[4];
    int tid = threadIdx.x;
    int is_key = (blockIdx.x >= 128);
    int bi = is_key ? (blockIdx.x - 128) : blockIdx.x;
    float tval = is_key ? timesteps[bi] : (float)bi * (1.0f / 127.0f);
    float ev;
    if (tid == 0) ev = tval * lin_w[0] + lin_b[0];
    else          ev = sinf(tval * per_w[tid - 1] + per_b[tid - 1]);
    emb[tid] = ev;
    __syncthreads();

    const float* wT   = is_key ? g_kwT : g_qwT;
    const float* bias = is_key ? k_b  : q_b;
    const float* gg   = is_key ? k_g  : q_g;
    const float* bb   = is_key ? k_be : q_be;
    float acc = bias[tid];
    #pragma unroll 8
    for (int i = 0; i < 128; i++) acc += emb[i] * wT[i * 128 + tid];

    float mean = block_sum_128(acc, red) * (1.0f / 128.0f);
    float d = acc - mean;
    float var = block_sum_128(d * d, red) * (1.0f / 128.0f);
    float y = d * rsqrtf(var + EPSLN) * gg[tid] + bb[tid];

    if (is_key) {
        int b = bi >> 9;
        int ti = bi & 511;
        g_kT[b * (128 * 512) + tid * 512 + ti] = y;
    } else {
        g_q[bi * 128 + tid] = y;
    }
}

// ---------------- fused scores + per-channel masked softmax attention ----------------
// block = (b, group of 8 queries). 128 threads. grid = 8*16 = 128.
__global__ __launch_bounds__(128) void attn_kernel(
    const float* __restrict__ input, const float* __restrict__ mask) {
    __shared__ float q_s[1024];      // 8 query rows x 128
    __shared__ float e_s[8 * 512];   // exp(scores) per query row
    __shared__ float wred[8 * 4];
    int tid = threadIdx.x;
    int b = blockIdx.x >> 4;
    int qg = blockIdx.x & 15;

    #pragma unroll
    for (int k = 0; k < 8; k++) q_s[tid + k * 128] = g_q[qg * 1024 + tid + k * 128];
    __syncthreads();

    float acc[8][4];
    #pragma unroll
    for (int j = 0; j < 8; j++)
        #pragma unroll
        for (int k = 0; k < 4; k++) acc[j][k] = 0.f;

    const float* kTb = g_kT + b * (128 * 512);
    int t0 = tid * 4;
    #pragma unroll 4
    for (int e = 0; e < 128; e++) {
        float4 kv = *reinterpret_cast<const float4*>(kTb + e * 512 + t0);
        #pragma unroll
        for (int j = 0; j < 8; j++) {
            float qv = q_s[j * 128 + e];
            acc[j][0] += qv * kv.x;
            acc[j][1] += qv * kv.y;
            acc[j][2] += qv * kv.z;
            acc[j][3] += qv * kv.w;
        }
    }
    const float scale = 0.08838834764831845f; // 1/sqrt(128)
    int warp = tid >> 5, lane = tid & 31;
    #pragma unroll
    for (int j = 0; j < 8; j++) {
        float m = fmaxf(fmaxf(acc[j][0], acc[j][1]), fmaxf(acc[j][2], acc[j][3]));
        #pragma unroll
        for (int o = 16; o > 0; o >>= 1) m = fmaxf(m, __shfl_xor_sync(0xffffffffu, m, o));
        if (lane == 0) wred[j * 4 + warp] = m;
    }
    __syncthreads();
    #pragma unroll
    for (int j = 0; j < 8; j++) {
        float M = fmaxf(fmaxf(wred[j * 4 + 0], wred[j * 4 + 1]),
                        fmaxf(wred[j * 4 + 2], wred[j * 4 + 3]));
        #pragma unroll
        for (int k = 0; k < 4; k++)
            e_s[j * 512 + t0 + k] = expf((acc[j][k] - M) * scale);
    }
    __syncthreads();

    // phase 2: per-channel masked weighted sum. 256 (c,j) tasks over 4 warps.
    for (int task = warp; task < 256; task += 4) {
        int c = task >> 3;
        int j = task & 7;
        const float* mrow = mask + (b * 32 + c) * 512;
        const float* irow = input + (b * 32 + c) * 512;
        const float* erow = e_s + j * 512;
        float num = 0.f, den = 0.f;
        #pragma unroll 4
        for (int t = lane; t < 512; t += 32) {
            float m = 1.0f - mrow[t];         // exactly 0 or 1
            float em = erow[t] * m;
            num += em * irow[t];              // x_in = m * input (m^2 = m)
            den += em;
        }
        #pragma unroll
        for (int o = 16; o > 0; o >>= 1) {
            num += __shfl_down_sync(0xffffffffu, num, o);
            den += __shfl_down_sync(0xffffffffu, den, o);
        }
        if (lane == 0) {
            int q = qg * 8 + j;
            float* arow = g_att + (b * 128 + q) * 64;
            arow[c]      = den > 0.f ? num / den : 0.f;
            arow[32 + c] = den > 0.f ? 1.f : 0.f;
        }
    }
}

// ---------------- attn LN -> out linear+LN -> GRU input gates ----------------
__global__ __launch_bounds__(128) void out_gi_kernel(
    const float* __restrict__ attn_g, const float* __restrict__ attn_b,
    const float* __restrict__ out_b, const float* __restrict__ out_g,
    const float* __restrict__ out_be, const float* __restrict__ gru_bih) {
    __shared__ float x2[64];
    __shared__ float o[128];
    __shared__ float red[4];
    int tid = threadIdx.x;
    int b = blockIdx.x >> 7;
    int nt = blockIdx.x & 127;

    const float* arow = g_att + blockIdx.x * 64;
    float v = (tid < 64) ? arow[tid] : 0.f;
    float mean = block_sum_128(v, red) * (1.0f / 64.0f);
    float d = (tid < 64) ? (v - mean) : 0.f;
    float var = block_sum_128(d * d, red) * (1.0f / 64.0f);
    if (tid < 64) x2[tid] = d * rsqrtf(var + EPSLN) * attn_g[tid] + attn_b[tid];
    __syncthreads();

    float acc = out_b[tid];
    #pragma unroll 8
    for (int i = 0; i < 64; i++) acc += x2[i] * g_outwT[i * 128 + tid];
    float mean2 = block_sum_128(acc, red) * (1.0f / 128.0f);
    float d2 = acc - mean2;
    float var2 = block_sum_128(d2 * d2, red) * (1.0f / 128.0f);
    o[tid] = d2 * rsqrtf(var2 + EPSLN) * out_g[tid] + out_be[tid];
    __syncthreads();

    float* girow = g_gi + (nt * 8 + b) * 384;
    #pragma unroll
    for (int k = 0; k < 3; k++) {
        int row = tid + k * 128;
        float a = gru_bih[row];
        #pragma unroll 8
        for (int i = 0; i < 128; i++) a += o[i] * g_wihT[i * 384 + row];
        girow[row] = a;
    }
}

// ---------------- GRU: one block per batch, Whh in registers ----------------
__global__ __launch_bounds__(384, 1) void gru_kernel(
    const float* __restrict__ whh, const float* __restrict__ bhh) {
    __shared__ float h_s[128];
    __shared__ float r_s[128], z_s[128], hn_s[128], gin_s[128];
    int tid = threadIdx.x;
    int b = blockIdx.x;

    float4 wr[32];
    const float4* wrow = reinterpret_cast<const float4*>(whh + tid * 128);
    #pragma unroll
    for (int i = 0; i < 32; i++) wr[i] = wrow[i];
    float bh = bhh[tid];
    if (tid < 128) h_s[tid] = 0.f;

    const float* gptr = g_gi + b * 384 + tid;
    int g = tid >> 7, j = tid & 127;

    for (int t = 0; t < 128; t++) {
        __syncthreads();
        float gival = gptr[t * 3072];
        float a0 = 0.f, a1 = 0.f, a2 = 0.f, a3 = 0.f;
        const float4* h4 = reinterpret_cast<const float4*>(h_s);
        #pragma unroll
        for (int i = 0; i < 32; i++) {
            float4 hv = h4[i];
            a0 += wr[i].x * hv.x;
            a1 += wr[i].y * hv.y;
            a2 += wr[i].z * hv.z;
            a3 += wr[i].w * hv.w;
        }
        float acc = (a0 + a1) + (a2 + a3) + bh;
        if (g == 0)      r_s[j] = acc + gival;
        else if (g == 1) z_s[j] = acc + gival;
        else           { hn_s[j] = acc; gin_s[j] = gival; }
        __syncthreads();
        if (tid < 128) {
            float r = 1.f / (1.f + expf(-r_s[tid]));
            float z = 1.f / (1.f + expf(-z_s[tid]));
            float n = tanhf(gin_s[tid] + r * hn_s[tid]);
            h_s[tid] = (1.f - z) * n + z * h_s[tid];
        }
    }
    __syncthreads();
    if (tid < 128) g_h[b * 128 + tid] = h_s[tid];
}

// ---------------- classifier MLP ----------------
__global__ __launch_bounds__(128) void cls_kernel(
    const float* __restrict__ c1b, const float* __restrict__ c2b,
    const float* __restrict__ c3w, const float* __restrict__ c3b,
    float* __restrict__ out) {
    __shared__ float hv[128], h1[128];
    int tid = threadIdx.x, b = blockIdx.x;
    hv[tid] = g_h[b * 128 + tid];
    __syncthreads();
    float a = c1b[tid];
    #pragma unroll 8
    for (int i = 0; i < 128; i++) a += hv[i] * g_c1T[i * 128 + tid];
    h1[tid] = fmaxf(a, 0.f);
    __syncthreads();
    float a2 = c2b[tid];
    #pragma unroll 8
    for (int i = 0; i < 128; i++) a2 += h1[i] * g_c2T[i * 128 + tid];
    __syncthreads();          // everyone done reading hv from layer 1
    hv[tid] = fmaxf(a2, 0.f);
    __syncthreads();
    if (tid < 2) {
        float a3 = c3b[tid];
        for (int i = 0; i < 128; i++) a3 += hv[i] * c3w[tid * 128 + i];
        out[b * 2 + tid] = a3;
    }
}

// ---------------- launch ----------------
extern "C" void kernel_launch(void* const* d_in, const int* in_sizes, int n_in,
                              void* d_out, int out_size) {
    const float* input  = (const float*)d_in[0];
    const float* mask   = (const float*)d_in[1];
    const float* tsteps = (const float*)d_in[2];
    const float* per_w  = (const float*)d_in[3];
    const float* per_b  = (const float*)d_in[4];
    const float* lin_w  = (const float*)d_in[5];
    const float* lin_b  = (const float*)d_in[6];
    const float* q_w    = (const float*)d_in[7];
    const float* q_b    = (const float*)d_in[8];
    const float* q_g    = (const float*)d_in[9];
    const float* q_be   = (const float*)d_in[10];
    const float* k_w    = (const float*)d_in[11];
    const float* k_b    = (const float*)d_in[12];
    const float* k_g    = (const float*)d_in[13];
    const float* k_be   = (const float*)d_in[14];
    const float* attn_g = (const float*)d_in[15];
    const float* attn_b = (const float*)d_in[16];
    const float* out_w  = (const float*)d_in[17];
    const float* out_b  = (const float*)d_in[18];
    const float* out_g  = (const float*)d_in[19];
    const float* out_be = (const float*)d_in[20];
    const float* wih    = (const float*)d_in[21];
    const float* whh    = (const float*)d_in[22];
    const float* bih    = (const float*)d_in[23];
    const float* bhh    = (const float*)d_in[24];
    const float* c1_w   = (const float*)d_in[25];
    const float* c1_b   = (const float*)d_in[26];
    const float* c2_w   = (const float*)d_in[27];
    const float* c2_b   = (const float*)d_in[28];
    const float* c3_w   = (const float*)d_in[29];
    const float* c3_b   = (const float*)d_in[30];
    float* out = (float*)d_out;

    tr_all_kernel<<<480, 256>>>(q_w, k_w, out_w, wih, c1_w, c2_w);
    proj_kernel<<<128 + 4096, 128>>>(tsteps, lin_w, lin_b, per_w, per_b,
                                     q_b, q_g, q_be, k_b, k_g, k_be);
    attn_kernel<<<128, 128>>>(input, mask);
    out_gi_kernel<<<1024, 128>>>(attn_g, attn_b, out_b, out_g, out_be, bih);
    gru_kernel<<<8, 384>>>(whh, bhh);
    cls_kernel<<<8, 128>>>(c1_b, c2_b, c3_w, c3_b, out);
}

// round 9
// speedup vs baseline: 1.1658x; 1.1658x over previous
#include <cuda_runtime.h>
#include <math.h>

#define EPSLN 1e-5f

// ---------------- device scratch ----------------
__device__ float g_qwT[128 * 128];
__device__ float g_kwT[128 * 128];
__device__ float g_outwT[64 * 128];
__device__ float g_wihT[128 * 384];
__device__ float g_c1T[128 * 128];
__device__ float g_c2T[128 * 128];
__device__ float g_q[128 * 128];        // (NT, E)
__device__ float g_kT[8 * 128 * 512];   // (B, E, T)
__device__ float g_att[8 * 128 * 64];   // (B, NT, 2F)
__device__ float g_gi[128 * 8 * 384];   // (t, b, 3H)
__device__ float g_h[8 * 128];

__device__ __forceinline__ float tanhfast(float x) {
    float y;
    asm("tanh.approx.f32 %0, %1;" : "=f"(y) : "f"(x));
    return y;
}
__device__ __forceinline__ float sigfast(float x) {
    return fmaf(0.5f, tanhfast(0.5f * x), 0.5f);
}

// ---------------- fused weight transpose ----------------
__global__ void tr_all_kernel(const float* __restrict__ qw, const float* __restrict__ kw,
                              const float* __restrict__ ow, const float* __restrict__ wih,
                              const float* __restrict__ c1, const float* __restrict__ c2) {
    int idx = blockIdx.x * 256 + threadIdx.x;
    if (idx < 16384) { g_qwT[(idx & 127) * 128 + (idx >> 7)] = qw[idx]; return; }
    idx -= 16384;
    if (idx < 16384) { g_kwT[(idx & 127) * 128 + (idx >> 7)] = kw[idx]; return; }
    idx -= 16384;
    if (idx < 8192)  { int r = idx >> 6, c = idx & 63; g_outwT[c * 128 + r] = ow[idx]; return; }
    idx -= 8192;
    if (idx < 49152) { int r = idx >> 7, c = idx & 127; g_wihT[c * 384 + r] = wih[idx]; return; }
    idx -= 49152;
    if (idx < 16384) { g_c1T[(idx & 127) * 128 + (idx >> 7)] = c1[idx]; return; }
    idx -= 16384;
    if (idx < 16384) { g_c2T[(idx & 127) * 128 + (idx >> 7)] = c2[idx]; return; }
}

// ---------------- proj: 16 rows per block, 256 threads ----------------
// blocks 0..7  : query rows 0..127
// blocks 8..263: key rows (idx = row-128 -> b=idx>>9, t=idx&511)
__global__ __launch_bounds__(256) void proj_kernel(
    const float* __restrict__ timesteps,
    const float* __restrict__ lin_w, const float* __restrict__ lin_b,
    const float* __restrict__ per_w, const float* __restrict__ per_b,
    const float* __restrict__ q_b, const float* __restrict__ q_g,
    const float* __restrict__ q_be,
    const float* __restrict__ k_b, const float* __restrict__ k_g,
    const float* __restrict__ k_be) {
    __shared__ float tv_s[16];
    __shared__ float emb_s[16 * 128];
    __shared__ float acc_s[16 * 128];
    int tid = threadIdx.x;
    int is_key = (blockIdx.x >= 8);
    int row0 = blockIdx.x * 16;

    if (tid < 16) {
        int u = row0 + tid;
        tv_s[tid] = is_key ? timesteps[u - 128] : (float)u * (1.0f / 127.0f);
    }
    __syncthreads();

    // embeddings: 16 x 128
    float lw = lin_w[0], lb = lin_b[0];
    #pragma unroll
    for (int s = 0; s < 8; s++) {
        int li = tid + s * 256;
        int r16 = li >> 7, col = li & 127;
        float tv = tv_s[r16];
        float ev = (col == 0) ? fmaf(tv, lw, lb)
                              : __sinf(fmaf(tv, per_w[col - 1], per_b[col - 1]));
        emb_s[li] = ev;
    }
    __syncthreads();

    // matmul: two row-groups of 8 rows; thread = col within group
    const float* wT   = is_key ? g_kwT : g_qwT;
    const float* bias = is_key ? k_b : q_b;
    int rg = tid >> 7, ltid = tid & 127;
    float acc[8];
    float bv = bias[ltid];
    #pragma unroll
    for (int r = 0; r < 8; r++) acc[r] = bv;
    const float* eb = emb_s + rg * 8 * 128;
    #pragma unroll 4
    for (int i = 0; i < 128; i++) {
        float wv = wT[i * 128 + ltid];
        #pragma unroll
        for (int r = 0; r < 8; r++) acc[r] = fmaf(eb[r * 128 + i], wv, acc[r]);
    }
    #pragma unroll
    for (int r = 0; r < 8; r++) acc_s[(rg * 8 + r) * 128 + ltid] = acc[r];
    __syncthreads();

    // LN: warp w handles rows {w, w+8}; lane covers cols lane+32k
    int warp = tid >> 5, lane = tid & 31;
    if (warp < 8) {
        const float* gg = is_key ? k_g : q_g;
        const float* bb = is_key ? k_be : q_be;
        #pragma unroll
        for (int rr = 0; rr < 2; rr++) {
            int r16 = warp + rr * 8;
            const float* arow = acc_s + r16 * 128;
            float v[4], s = 0.f, sq = 0.f;
            #pragma unroll
            for (int k = 0; k < 4; k++) {
                v[k] = arow[lane + 32 * k];
                s += v[k];
                sq = fmaf(v[k], v[k], sq);
            }
            #pragma unroll
            for (int o = 16; o > 0; o >>= 1) {
                s  += __shfl_xor_sync(0xffffffffu, s, o);
                sq += __shfl_xor_sync(0xffffffffu, sq, o);
            }
            float mean = s * (1.0f / 128.0f);
            float var = sq * (1.0f / 128.0f) - mean * mean;
            float rs = rsqrtf(var + EPSLN);
            int u = row0 + r16;
            #pragma unroll
            for (int k = 0; k < 4; k++) {
                int col = lane + 32 * k;
                float y = fmaf((v[k] - mean) * rs, gg[col], bb[col]);
                if (is_key) {
                    int idx = u - 128;
                    int b = idx >> 9, t = idx & 511;
                    g_kT[b * 65536 + col * 512 + t] = y;
                } else {
                    g_q[u * 128 + col] = y;
                }
            }
        }
    }
}

// ---------------- fused scores + per-channel masked softmax attention ----------------
__global__ __launch_bounds__(128) void attn_kernel(
    const float* __restrict__ input, const float* __restrict__ mask) {
    __shared__ float q_s[1024];
    __shared__ float e_s[8 * 512];
    __shared__ float wred[8 * 4];
    int tid = threadIdx.x;
    int b = blockIdx.x >> 4;
    int qg = blockIdx.x & 15;

    #pragma unroll
    for (int k = 0; k < 8; k++) q_s[tid + k * 128] = g_q[qg * 1024 + tid + k * 128];
    __syncthreads();

    float acc[8][4];
    #pragma unroll
    for (int j = 0; j < 8; j++)
        #pragma unroll
        for (int k = 0; k < 4; k++) acc[j][k] = 0.f;

    const float* kTb = g_kT + b * (128 * 512);
    int t0 = tid * 4;
    #pragma unroll 4
    for (int e = 0; e < 128; e++) {
        float4 kv = *reinterpret_cast<const float4*>(kTb + e * 512 + t0);
        #pragma unroll
        for (int j = 0; j < 8; j++) {
            float qv = q_s[j * 128 + e];
            acc[j][0] = fmaf(qv, kv.x, acc[j][0]);
            acc[j][1] = fmaf(qv, kv.y, acc[j][1]);
            acc[j][2] = fmaf(qv, kv.z, acc[j][2]);
            acc[j][3] = fmaf(qv, kv.w, acc[j][3]);
        }
    }
    const float scale = 0.08838834764831845f; // 1/sqrt(128)
    int warp = tid >> 5, lane = tid & 31;
    #pragma unroll
    for (int j = 0; j < 8; j++) {
        float m = fmaxf(fmaxf(acc[j][0], acc[j][1]), fmaxf(acc[j][2], acc[j][3]));
        #pragma unroll
        for (int o = 16; o > 0; o >>= 1) m = fmaxf(m, __shfl_xor_sync(0xffffffffu, m, o));
        if (lane == 0) wred[j * 4 + warp] = m;
    }
    __syncthreads();
    #pragma unroll
    for (int j = 0; j < 8; j++) {
        float M = fmaxf(fmaxf(wred[j * 4 + 0], wred[j * 4 + 1]),
                        fmaxf(wred[j * 4 + 2], wred[j * 4 + 3]));
        #pragma unroll
        for (int k = 0; k < 4; k++)
            e_s[j * 512 + t0 + k] = __expf((acc[j][k] - M) * scale);
    }
    __syncthreads();

    // phase 2: c outer (register-cached mask/input), j inner
    for (int c = warp; c < 32; c += 4) {
        const float* mrow = mask + (b * 32 + c) * 512;
        const float* irow = input + (b * 32 + c) * 512;
        float mv[16], miv[16];
        #pragma unroll
        for (int s = 0; s < 16; s++) {
            int t = lane + s * 32;
            float m = 1.0f - mrow[t];
            mv[s] = m;
            miv[s] = m * irow[t];
        }
        #pragma unroll
        for (int j = 0; j < 8; j++) {
            const float* erow = e_s + j * 512 + lane;
            float num = 0.f, den = 0.f;
            #pragma unroll
            for (int s = 0; s < 16; s++) {
                float e = erow[s * 32];
                num = fmaf(e, miv[s], num);
                den = fmaf(e, mv[s], den);
            }
            #pragma unroll
            for (int o = 16; o > 0; o >>= 1) {
                num += __shfl_down_sync(0xffffffffu, num, o);
                den += __shfl_down_sync(0xffffffffu, den, o);
            }
            if (lane == 0) {
                int q = qg * 8 + j;
                float* arow = g_att + (b * 128 + q) * 64;
                arow[c]      = den > 0.f ? num / den : 0.f;
                arow[32 + c] = den > 0.f ? 1.f : 0.f;
            }
        }
    }
}

// ---------------- attn LN -> out linear+LN -> GRU input gates (8 rows/block) ----------------
__global__ __launch_bounds__(384) void out_gi_kernel(
    const float* __restrict__ attn_g, const float* __restrict__ attn_b,
    const float* __restrict__ out_b, const float* __restrict__ out_g,
    const float* __restrict__ out_be, const float* __restrict__ gru_bih) {
    __shared__ float x2_s[8 * 64];
    __shared__ float o_s[8 * 128];
    int tid = threadIdx.x;
    int warp = tid >> 5, lane = tid & 31;
    int rid0 = blockIdx.x * 8;

    if (warp < 8) {
        int rid = rid0 + warp;
        // LN over att row (64)
        const float2* arow = reinterpret_cast<const float2*>(g_att + rid * 64);
        float2 v = arow[lane];
        float s = v.x + v.y;
        float sq = fmaf(v.x, v.x, v.y * v.y);
        #pragma unroll
        for (int o = 16; o > 0; o >>= 1) {
            s  += __shfl_xor_sync(0xffffffffu, s, o);
            sq += __shfl_xor_sync(0xffffffffu, sq, o);
        }
        float mean = s * (1.0f / 64.0f);
        float var = sq * (1.0f / 64.0f) - mean * mean;
        float rs = rsqrtf(var + EPSLN);
        x2_s[warp * 64 + lane * 2]     = fmaf((v.x - mean) * rs, attn_g[lane * 2], attn_b[lane * 2]);
        x2_s[warp * 64 + lane * 2 + 1] = fmaf((v.y - mean) * rs, attn_g[lane * 2 + 1], attn_b[lane * 2 + 1]);
        __syncwarp();

        // out linear (128 cols, 4 per lane) + LN
        float acc[4], s2 = 0.f, sq2 = 0.f;
        #pragma unroll
        for (int k = 0; k < 4; k++) acc[k] = out_b[lane + 32 * k];
        const float* x2r = x2_s + warp * 64;
        #pragma unroll 4
        for (int i = 0; i < 64; i++) {
            float x = x2r[i];
            #pragma unroll
            for (int k = 0; k < 4; k++)
                acc[k] = fmaf(x, g_outwT[i * 128 + lane + 32 * k], acc[k]);
        }
        #pragma unroll
        for (int k = 0; k < 4; k++) { s2 += acc[k]; sq2 = fmaf(acc[k], acc[k], sq2); }
        #pragma unroll
        for (int o = 16; o > 0; o >>= 1) {
            s2  += __shfl_xor_sync(0xffffffffu, s2, o);
            sq2 += __shfl_xor_sync(0xffffffffu, sq2, o);
        }
        float mean2 = s2 * (1.0f / 128.0f);
        float var2 = sq2 * (1.0f / 128.0f) - mean2 * mean2;
        float rs2 = rsqrtf(var2 + EPSLN);
        #pragma unroll
        for (int k = 0; k < 4; k++) {
            int col = lane + 32 * k;
            o_s[warp * 128 + col] = fmaf((acc[k] - mean2) * rs2, out_g[col], out_be[col]);
        }
    }
    __syncthreads();

    // gi GEMM: thread = output col (384), 8 rows
    float acc[8];
    float bv = gru_bih[tid];
    #pragma unroll
    for (int r = 0; r < 8; r++) acc[r] = bv;
    #pragma unroll 4
    for (int i = 0; i < 128; i++) {
        float wv = g_wihT[i * 384 + tid];
        #pragma unroll
        for (int r = 0; r < 8; r++) acc[r] = fmaf(o_s[r * 128 + i], wv, acc[r]);
    }
    #pragma unroll
    for (int r = 0; r < 8; r++) {
        int rid = rid0 + r;
        int b = rid >> 7, nt = rid & 127;
        g_gi[(nt * 8 + b) * 384 + tid] = acc[r];
    }
}

// ---------------- GRU: one block per batch, Whh in registers ----------------
__global__ __launch_bounds__(384, 1) void gru_kernel(
    const float* __restrict__ whh, const float* __restrict__ bhh) {
    __shared__ float h_s[128];
    __shared__ float r_s[128], z_s[128], hn_s[128], gin_s[128];
    int tid = threadIdx.x;
    int b = blockIdx.x;

    float4 wr[32];
    const float4* wrow = reinterpret_cast<const float4*>(whh + tid * 128);
    #pragma unroll
    for (int i = 0; i < 32; i++) wr[i] = wrow[i];
    float bh = bhh[tid];
    if (tid < 128) h_s[tid] = 0.f;

    const float* gptr = g_gi + b * 384 + tid;
    int g = tid >> 7, j = tid & 127;

    for (int t = 0; t < 128; t++) {
        __syncthreads();
        float gival = gptr[t * 3072];
        float a[8];
        #pragma unroll
        for (int k = 0; k < 8; k++) a[k] = 0.f;
        const float4* h4 = reinterpret_cast<const float4*>(h_s);
        #pragma unroll
        for (int i = 0; i < 32; i += 2) {
            float4 h0 = h4[i], h1 = h4[i + 1];
            a[0] = fmaf(wr[i].x, h0.x, a[0]);
            a[1] = fmaf(wr[i].y, h0.y, a[1]);
            a[2] = fmaf(wr[i].z, h0.z, a[2]);
            a[3] = fmaf(wr[i].w, h0.w, a[3]);
            a[4] = fmaf(wr[i + 1].x, h1.x, a[4]);
            a[5] = fmaf(wr[i + 1].y, h1.y, a[5]);
            a[6] = fmaf(wr[i + 1].z, h1.z, a[6]);
            a[7] = fmaf(wr[i + 1].w, h1.w, a[7]);
        }
        float accv = ((a[0] + a[4]) + (a[1] + a[5])) + ((a[2] + a[6]) + (a[3] + a[7])) + bh;
        if (g == 0)      r_s[j] = accv + gival;
        else if (g == 1) z_s[j] = accv + gival;
        else           { hn_s[j] = accv; gin_s[j] = gival; }
        __syncthreads();
        if (tid < 128) {
            float r = sigfast(r_s[tid]);
            float z = sigfast(z_s[tid]);
            float n = tanhfast(fmaf(r, hn_s[tid], gin_s[tid]));
            h_s[tid] = fmaf(z, h_s[tid] - n, n);
        }
    }
    __syncthreads();
    if (tid < 128) g_h[b * 128 + tid] = h_s[tid];
}

// ---------------- classifier MLP ----------------
__global__ __launch_bounds__(128) void cls_kernel(
    const float* __restrict__ c1b, const float* __restrict__ c2b,
    const float* __restrict__ c3w, const float* __restrict__ c3b,
    float* __restrict__ out) {
    __shared__ float hv[128], h1[128];
    int tid = threadIdx.x, b = blockIdx.x;
    hv[tid] = g_h[b * 128 + tid];
    __syncthreads();
    float a = c1b[tid];
    #pragma unroll 8
    for (int i = 0; i < 128; i++) a = fmaf(hv[i], g_c1T[i * 128 + tid], a);
    h1[tid] = fmaxf(a, 0.f);
    __syncthreads();
    float a2 = c2b[tid];
    #pragma unroll 8
    for (int i = 0; i < 128; i++) a2 = fmaf(h1[i], g_c2T[i * 128 + tid], a2);
    __syncthreads();
    hv[tid] = fmaxf(a2, 0.f);
    __syncthreads();
    if (tid < 2) {
        float a3 = c3b[tid];
        for (int i = 0; i < 128; i++) a3 = fmaf(hv[i], c3w[tid * 128 + i], a3);
        out[b * 2 + tid] = a3;
    }
}

// ---------------- launch ----------------
extern "C" void kernel_launch(void* const* d_in, const int* in_sizes, int n_in,
                              void* d_out, int out_size) {
    const float* input  = (const float*)d_in[0];
    const float* mask   = (const float*)d_in[1];
    const float* tsteps = (const float*)d_in[2];
    const float* per_w  = (const float*)d_in[3];
    const float* per_b  = (const float*)d_in[4];
    const float* lin_w  = (const float*)d_in[5];
    const float* lin_b  = (const float*)d_in[6];
    const float* q_w    = (const float*)d_in[7];
    const float* q_b    = (const float*)d_in[8];
    const float* q_g    = (const float*)d_in[9];
    const float* q_be   = (const float*)d_in[10];
    const float* k_w    = (const float*)d_in[11];
    const float* k_b    = (const float*)d_in[12];
    const float* k_g    = (const float*)d_in[13];
    const float* k_be   = (const float*)d_in[14];
    const float* attn_g = (const float*)d_in[15];
    const float* attn_b = (const float*)d_in[16];
    const float* out_w  = (const float*)d_in[17];
    const float* out_b  = (const float*)d_in[18];
    const float* out_g  = (const float*)d_in[19];
    const float* out_be = (const float*)d_in[20];
    const float* wih    = (const float*)d_in[21];
    const float* whh    = (const float*)d_in[22];
    const float* bih    = (const float*)d_in[23];
    const float* bhh    = (const float*)d_in[24];
    const float* c1_w   = (const float*)d_in[25];
    const float* c1_b   = (const float*)d_in[26];
    const float* c2_w   = (const float*)d_in[27];
    const float* c2_b   = (const float*)d_in[28];
    const float* c3_w   = (const float*)d_in[29];
    const float* c3_b   = (const float*)d_in[30];
    float* out = (float*)d_out;

    tr_all_kernel<<<480, 256>>>(q_w, k_w, out_w, wih, c1_w, c2_w);
    proj_kernel<<<264, 256>>>(tsteps, lin_w, lin_b, per_w, per_b,
                              q_b, q_g, q_be, k_b, k_g, k_be);
    attn_kernel<<<128, 128>>>(input, mask);
    out_gi_kernel<<<128, 384>>>(attn_g, attn_b, out_b, out_g, out_be, bih);
    gru_kernel<<<8, 384>>>(whh, bhh);
    cls_kernel<<<8, 128>>>(c1_b, c2_b, c3_w, c3_b, out);
}

// round 12
// speedup vs baseline: 1.3998x; 1.2007x over previous
#include <cuda_runtime.h>
#include <math.h>

#define EPSLN 1e-5f

// ---------------- device scratch ----------------
__device__ float g_qwT[128 * 128];
__device__ float g_kwT[128 * 128];
__device__ float g_outwT[64 * 128];
__device__ float g_wihT[128 * 384];
__device__ float g_c1T[128 * 128];
__device__ float g_c2T[128 * 128];
__device__ float g_q[128 * 128];        // (NT, E)
__device__ float g_kT[8 * 128 * 512];   // (B, E, T)
__device__ float g_att[8 * 128 * 64];   // (B, NT, 2F)
__device__ float g_gi[128 * 8 * 384];   // (t, b, 3H)

typedef unsigned long long u64;

__device__ __forceinline__ float tanhfast(float x) {
    float y;
    asm("tanh.approx.f32 %0, %1;" : "=f"(y) : "f"(x));
    return y;
}
__device__ __forceinline__ float sigfast(float x) {
    return fmaf(0.5f, tanhfast(0.5f * x), 0.5f);
}
__device__ __forceinline__ u64 fma2(u64 a, u64 b, u64 c) {
    u64 d;
    asm("fma.rn.f32x2 %0, %1, %2, %3;" : "=l"(d) : "l"(a), "l"(b), "l"(c));
    return d;
}
__device__ __forceinline__ u64 add2(u64 a, u64 b) {
    u64 d;
    asm("add.rn.f32x2 %0, %1, %2;" : "=l"(d) : "l"(a), "l"(b));
    return d;
}
__device__ __forceinline__ u64 pack2(float lo, float hi) {
    u64 r;
    asm("mov.b64 %0, {%1,%2};" : "=l"(r) : "f"(lo), "f"(hi));
    return r;
}
__device__ __forceinline__ float2 unpack2(u64 v) {
    float2 f;
    asm("mov.b64 {%0,%1}, %2;" : "=f"(f.x), "=f"(f.y) : "l"(v));
    return f;
}

// ---------------- fused weight transpose ----------------
__global__ void tr_all_kernel(const float* __restrict__ qw, const float* __restrict__ kw,
                              const float* __restrict__ ow, const float* __restrict__ wih,
                              const float* __restrict__ c1, const float* __restrict__ c2) {
    int idx = blockIdx.x * 256 + threadIdx.x;
    if (idx < 16384) { g_qwT[(idx & 127) * 128 + (idx >> 7)] = qw[idx]; return; }
    idx -= 16384;
    if (idx < 16384) { g_kwT[(idx & 127) * 128 + (idx >> 7)] = kw[idx]; return; }
    idx -= 16384;
    if (idx < 8192)  { int r = idx >> 6, c = idx & 63; g_outwT[c * 128 + r] = ow[idx]; return; }
    idx -= 8192;
    if (idx < 49152) { int r = idx >> 7, c = idx & 127; g_wihT[c * 384 + r] = wih[idx]; return; }
    idx -= 49152;
    if (idx < 16384) { g_c1T[(idx & 127) * 128 + (idx >> 7)] = c1[idx]; return; }
    idx -= 16384;
    if (idx < 16384) { g_c2T[(idx & 127) * 128 + (idx >> 7)] = c2[idx]; return; }
}

// ---------------- proj: 16 rows per block, 256 threads ----------------
__global__ __launch_bounds__(256) void proj_kernel(
    const float* __restrict__ timesteps,
    const float* __restrict__ lin_w, const float* __restrict__ lin_b,
    const float* __restrict__ per_w, const float* __restrict__ per_b,
    const float* __restrict__ q_b, const float* __restrict__ q_g,
    const float* __restrict__ q_be,
    const float* __restrict__ k_b, const float* __restrict__ k_g,
    const float* __restrict__ k_be) {
    __shared__ float tv_s[16];
    __shared__ float emb_s[16 * 128];
    __shared__ float acc_s[16 * 128];
    int tid = threadIdx.x;
    int is_key = (blockIdx.x >= 8);
    int row0 = blockIdx.x * 16;

    if (tid < 16) {
        int u = row0 + tid;
        tv_s[tid] = is_key ? timesteps[u - 128] : (float)u * (1.0f / 127.0f);
    }
    __syncthreads();

    float lw = lin_w[0], lb = lin_b[0];
    #pragma unroll
    for (int s = 0; s < 8; s++) {
        int li = tid + s * 256;
        int r16 = li >> 7, col = li & 127;
        float tv = tv_s[r16];
        float ev = (col == 0) ? fmaf(tv, lw, lb)
                              : __sinf(fmaf(tv, per_w[col - 1], per_b[col - 1]));
        emb_s[li] = ev;
    }
    __syncthreads();

    const float* wT   = is_key ? g_kwT : g_qwT;
    const float* bias = is_key ? k_b : q_b;
    int rg = tid >> 7, ltid = tid & 127;
    float acc[8];
    float bv = bias[ltid];
    #pragma unroll
    for (int r = 0; r < 8; r++) acc[r] = bv;
    const float* eb = emb_s + rg * 8 * 128;
    #pragma unroll 8
    for (int i = 0; i < 128; i++) {
        float wv = wT[i * 128 + ltid];
        #pragma unroll
        for (int r = 0; r < 8; r++) acc[r] = fmaf(eb[r * 128 + i], wv, acc[r]);
    }
    #pragma unroll
    for (int r = 0; r < 8; r++) acc_s[(rg * 8 + r) * 128 + ltid] = acc[r];
    __syncthreads();

    int warp = tid >> 5, lane = tid & 31;
    if (warp < 8) {
        const float* gg = is_key ? k_g : q_g;
        const float* bb = is_key ? k_be : q_be;
        #pragma unroll
        for (int rr = 0; rr < 2; rr++) {
            int r16 = warp + rr * 8;
            const float* arow = acc_s + r16 * 128;
            float v[4], s = 0.f, sq = 0.f;
            #pragma unroll
            for (int k = 0; k < 4; k++) {
                v[k] = arow[lane + 32 * k];
                s += v[k];
                sq = fmaf(v[k], v[k], sq);
            }
            #pragma unroll
            for (int o = 16; o > 0; o >>= 1) {
                s  += __shfl_xor_sync(0xffffffffu, s, o);
                sq += __shfl_xor_sync(0xffffffffu, sq, o);
            }
            float mean = s * (1.0f / 128.0f);
            float var = sq * (1.0f / 128.0f) - mean * mean;
            float rs = rsqrtf(var + EPSLN);
            int u = row0 + r16;
            #pragma unroll
            for (int k = 0; k < 4; k++) {
                int col = lane + 32 * k;
                float y = fmaf((v[k] - mean) * rs, gg[col], bb[col]);
                if (is_key) {
                    int idx = u - 128;
                    int b = idx >> 9, t = idx & 511;
                    g_kT[b * 65536 + col * 512 + t] = y;
                } else {
                    g_q[u * 128 + col] = y;
                }
            }
        }
    }
}

// ---------------- attention: 256 threads, f32x2 scores ----------------
__global__ __launch_bounds__(256) void attn_kernel(
    const float* __restrict__ input, const float* __restrict__ mask) {
    __shared__ u64 q_p[8 * 128];     // packed (q,q), 8KB
    __shared__ float e_s[8 * 512];   // 16KB
    __shared__ float wred[8 * 8];
    int tid = threadIdx.x;
    int b = blockIdx.x >> 4;
    int qg = blockIdx.x & 15;
    int warp = tid >> 5, lane = tid & 31;

    #pragma unroll
    for (int s = 0; s < 4; s++) {
        int idx = tid + s * 256;
        float v = g_q[qg * 1024 + idx];
        q_p[idx] = pack2(v, v);
    }
    __syncthreads();

    // scores: thread covers keys t0, t0+1 for all 8 queries
    u64 acc2[8];
    #pragma unroll
    for (int j = 0; j < 8; j++) acc2[j] = 0ull;
    const u64* kTb = reinterpret_cast<const u64*>(g_kT + b * 65536);
    #pragma unroll 8
    for (int e = 0; e < 128; e++) {
        u64 kv = kTb[e * 256 + tid];
        #pragma unroll
        for (int j = 0; j < 8; j++)
            acc2[j] = fma2(q_p[j * 128 + e], kv, acc2[j]);
    }
    const float scale = 0.08838834764831845f; // 1/sqrt(128)
    int t0 = tid * 2;
    #pragma unroll
    for (int j = 0; j < 8; j++) {
        float2 a = unpack2(acc2[j]);
        float m = fmaxf(a.x, a.y);
        #pragma unroll
        for (int o = 16; o > 0; o >>= 1) m = fmaxf(m, __shfl_xor_sync(0xffffffffu, m, o));
        if (lane == 0) wred[j * 8 + warp] = m;
    }
    __syncthreads();
    #pragma unroll
    for (int j = 0; j < 8; j++) {
        float M = wred[j * 8];
        #pragma unroll
        for (int w = 1; w < 8; w++) M = fmaxf(M, wred[j * 8 + w]);
        float2 a = unpack2(acc2[j]);
        e_s[j * 512 + t0]     = __expf((a.x - M) * scale);
        e_s[j * 512 + t0 + 1] = __expf((a.y - M) * scale);
    }
    __syncthreads();

    // phase 2: channel outer (register-cached mask/input), query inner
    for (int c = warp; c < 32; c += 8) {
        const float* mrow = mask + (b * 32 + c) * 512;
        const float* irow = input + (b * 32 + c) * 512;
        float mv[16], miv[16];
        #pragma unroll
        for (int s = 0; s < 16; s++) {
            int t = lane + s * 32;
            float m = 1.0f - mrow[t];
            mv[s] = m;
            miv[s] = m * irow[t];
        }
        #pragma unroll
        for (int j = 0; j < 8; j++) {
            const float* erow = e_s + j * 512 + lane;
            float num = 0.f, den = 0.f;
            #pragma unroll
            for (int s = 0; s < 16; s++) {
                float e = erow[s * 32];
                num = fmaf(e, miv[s], num);
                den = fmaf(e, mv[s], den);
            }
            #pragma unroll
            for (int o = 16; o > 0; o >>= 1) {
                num += __shfl_down_sync(0xffffffffu, num, o);
                den += __shfl_down_sync(0xffffffffu, den, o);
            }
            if (lane == 0) {
                int q = qg * 8 + j;
                float* arow = g_att + (b * 128 + q) * 64;
                arow[c]      = den > 0.f ? num / den : 0.f;
                arow[32 + c] = den > 0.f ? 1.f : 0.f;
            }
        }
    }
}

// ---------------- attn LN -> out linear+LN -> gi GEMM (smem-tiled, f32x2) ----------------
__global__ __launch_bounds__(384) void out_gi_kernel(
    const float* __restrict__ attn_g, const float* __restrict__ attn_b,
    const float* __restrict__ out_b, const float* __restrict__ out_g,
    const float* __restrict__ out_be, const float* __restrict__ gru_bih) {
    __shared__ float x2_s[8 * 64];
    __shared__ float o_s[8 * 128];
    __shared__ u64 o_p[4 * 128];     // packed rows (r, r+4)
    __shared__ float w_s[16 * 384];  // 24KB tile
    int tid = threadIdx.x;
    int warp = tid >> 5, lane = tid & 31;
    int rid0 = blockIdx.x * 8;

    if (warp < 8) {
        int rid = rid0 + warp;
        const float2* arow = reinterpret_cast<const float2*>(g_att + rid * 64);
        float2 v = arow[lane];
        float s = v.x + v.y;
        float sq = fmaf(v.x, v.x, v.y * v.y);
        #pragma unroll
        for (int o = 16; o > 0; o >>= 1) {
            s  += __shfl_xor_sync(0xffffffffu, s, o);
            sq += __shfl_xor_sync(0xffffffffu, sq, o);
        }
        float mean = s * (1.0f / 64.0f);
        float var = sq * (1.0f / 64.0f) - mean * mean;
        float rs = rsqrtf(var + EPSLN);
        x2_s[warp * 64 + lane * 2]     = fmaf((v.x - mean) * rs, attn_g[lane * 2], attn_b[lane * 2]);
        x2_s[warp * 64 + lane * 2 + 1] = fmaf((v.y - mean) * rs, attn_g[lane * 2 + 1], attn_b[lane * 2 + 1]);
        __syncwarp();

        float acc[4], s2 = 0.f, sq2 = 0.f;
        #pragma unroll
        for (int k = 0; k < 4; k++) acc[k] = out_b[lane + 32 * k];
        const float* x2r = x2_s + warp * 64;
        #pragma unroll 8
        for (int i = 0; i < 64; i++) {
            float x = x2r[i];
            #pragma unroll
            for (int k = 0; k < 4; k++)
                acc[k] = fmaf(x, g_outwT[i * 128 + lane + 32 * k], acc[k]);
        }
        #pragma unroll
        for (int k = 0; k < 4; k++) { s2 += acc[k]; sq2 = fmaf(acc[k], acc[k], sq2); }
        #pragma unroll
        for (int o = 16; o > 0; o >>= 1) {
            s2  += __shfl_xor_sync(0xffffffffu, s2, o);
            sq2 += __shfl_xor_sync(0xffffffffu, sq2, o);
        }
        float mean2 = s2 * (1.0f / 128.0f);
        float var2 = sq2 * (1.0f / 128.0f) - mean2 * mean2;
        float rs2 = rsqrtf(var2 + EPSLN);
        #pragma unroll
        for (int k = 0; k < 4; k++) {
            int col = lane + 32 * k;
            o_s[warp * 128 + col] = fmaf((acc[k] - mean2) * rs2, out_g[col], out_be[col]);
        }
    }
    __syncthreads();

    // pack row pairs (r, r+4)
    for (int idx = tid; idx < 512; idx += 384) {
        int r2 = idx >> 7, i = idx & 127;
        o_p[idx] = pack2(o_s[r2 * 128 + i], o_s[(r2 + 4) * 128 + i]);
    }

    // gi GEMM: thread = output col, 8 tiles of 16 i, weights via smem
    u64 acc2[4];
    float bv = gru_bih[tid];
    #pragma unroll
    for (int r2 = 0; r2 < 4; r2++) acc2[r2] = pack2(bv, bv);
    #pragma unroll 1
    for (int tile = 0; tile < 8; tile++) {
        __syncthreads();
        const float4* src = reinterpret_cast<const float4*>(g_wihT + tile * 16 * 384);
        float4* dst = reinterpret_cast<float4*>(w_s);
        #pragma unroll
        for (int k2 = 0; k2 < 4; k2++) dst[tid + k2 * 384] = src[tid + k2 * 384];
        __syncthreads();
        #pragma unroll
        for (int i = 0; i < 16; i++) {
            float wv = w_s[i * 384 + tid];
            u64 w2 = pack2(wv, wv);
            int ii = tile * 16 + i;
            #pragma unroll
            for (int r2 = 0; r2 < 4; r2++)
                acc2[r2] = fma2(o_p[r2 * 128 + ii], w2, acc2[r2]);
        }
    }
    #pragma unroll
    for (int r2 = 0; r2 < 4; r2++) {
        float2 f = unpack2(acc2[r2]);
        int ridA = rid0 + r2, ridB = rid0 + r2 + 4;
        g_gi[(((ridA & 127) * 8) + (ridA >> 7)) * 384 + tid] = f.x;
        g_gi[(((ridB & 127) * 8) + (ridB >> 7)) * 384 + tid] = f.y;
    }
}

// ---------------- GRU (f32x2, gi prefetch) + classifier, one block/batch ----------------
__global__ __launch_bounds__(384, 1) void gru_cls_kernel(
    const float* __restrict__ whh, const float* __restrict__ bhh,
    const float* __restrict__ c1b, const float* __restrict__ c2b,
    const float* __restrict__ c3w, const float* __restrict__ c3b,
    float* __restrict__ out) {
    __shared__ __align__(16) float h_s[128];
    __shared__ float r_s[128], z_s[128], hn_s[128], gin_s[128];
    int tid = threadIdx.x;
    int b = blockIdx.x;

    u64 wp[64];
    const u64* wrow = reinterpret_cast<const u64*>(whh + tid * 128);
    #pragma unroll
    for (int i = 0; i < 64; i++) wp[i] = wrow[i];
    float bh = bhh[tid];
    if (tid < 128) h_s[tid] = 0.f;

    const float* gptr = g_gi + b * 384 + tid;
    int g = tid >> 7, j = tid & 127;
    float giv = gptr[0];

    for (int t = 0; t < 128; t++) {
        __syncthreads();
        float giv_next = (t < 127) ? gptr[(t + 1) * 3072] : 0.f;
        u64 a2[4];
        #pragma unroll
        for (int k = 0; k < 4; k++) a2[k] = 0ull;
        const ulonglong2* h2 = reinterpret_cast<const ulonglong2*>(h_s);
        #pragma unroll
        for (int i = 0; i < 32; i += 2) {
            ulonglong2 hv0 = h2[i], hv1 = h2[i + 1];
            a2[0] = fma2(wp[2 * i],     hv0.x, a2[0]);
            a2[1] = fma2(wp[2 * i + 1], hv0.y, a2[1]);
            a2[2] = fma2(wp[2 * i + 2], hv1.x, a2[2]);
            a2[3] = fma2(wp[2 * i + 3], hv1.y, a2[3]);
        }
        a2[0] = add2(a2[0], a2[1]);
        a2[2] = add2(a2[2], a2[3]);
        a2[0] = add2(a2[0], a2[2]);
        float2 f = unpack2(a2[0]);
        float accv = f.x + f.y + bh;
        if (g == 0)      r_s[j] = accv + giv;
        else if (g == 1) z_s[j] = accv + giv;
        else           { hn_s[j] = accv; gin_s[j] = giv; }
        __syncthreads();
        if (tid < 128) {
            float r = sigfast(r_s[tid]);
            float z = sigfast(z_s[tid]);
            float n = tanhfast(fmaf(r, hn_s[tid], gin_s[tid]));
            h_s[tid] = fmaf(z, h_s[tid] - n, n);
        }
        giv = giv_next;
    }
    __syncthreads();

    // classifier on h_s
    if (tid < 128) {
        float a = c1b[tid];
        #pragma unroll 8
        for (int i = 0; i < 128; i++) a = fmaf(h_s[i], g_c1T[i * 128 + tid], a);
        r_s[tid] = fmaxf(a, 0.f);
    }
    __syncthreads();
    if (tid < 128) {
        float a2v = c2b[tid];
        #pragma unroll 8
        for (int i = 0; i < 128; i++) a2v = fmaf(r_s[i], g_c2T[i * 128 + tid], a2v);
        z_s[tid] = fmaxf(a2v, 0.f);
    }
    __syncthreads();
    if (tid < 2) {
        float a3 = c3b[tid];
        #pragma unroll 8
        for (int i = 0; i < 128; i++) a3 = fmaf(z_s[i], c3w[tid * 128 + i], a3);
        out[b * 2 + tid] = a3;
    }
}

// ---------------- launch ----------------
extern "C" void kernel_launch(void* const* d_in, const int* in_sizes, int n_in,
                              void* d_out, int out_size) {
    const float* input  = (const float*)d_in[0];
    const float* mask   = (const float*)d_in[1];
    const float* tsteps = (const float*)d_in[2];
    const float* per_w  = (const float*)d_in[3];
    const float* per_b  = (const float*)d_in[4];
    const float* lin_w  = (const float*)d_in[5];
    const float* lin_b  = (const float*)d_in[6];
    const float* q_w    = (const float*)d_in[7];
    const float* q_b    = (const float*)d_in[8];
    const float* q_g    = (const float*)d_in[9];
    const float* q_be   = (const float*)d_in[10];
    const float* k_w    = (const float*)d_in[11];
    const float* k_b    = (const float*)d_in[12];
    const float* k_g    = (const float*)d_in[13];
    const float* k_be   = (const float*)d_in[14];
    const float* attn_g = (const float*)d_in[15];
    const float* attn_b = (const float*)d_in[16];
    const float* out_w  = (const float*)d_in[17];
    const float* out_b  = (const float*)d_in[18];
    const float* out_g  = (const float*)d_in[19];
    const float* out_be = (const float*)d_in[20];
    const float* wih    = (const float*)d_in[21];
    const float* whh    = (const float*)d_in[22];
    const float* bih    = (const float*)d_in[23];
    const float* bhh    = (const float*)d_in[24];
    const float* c1_w   = (const float*)d_in[25];
    const float* c1_b   = (const float*)d_in[26];
    const float* c2_w   = (const float*)d_in[27];
    const float* c2_b   = (const float*)d_in[28];
    const float* c3_w   = (const float*)d_in[29];
    const float* c3_b   = (const float*)d_in[30];
    float* out = (float*)d_out;

    tr_all_kernel<<<480, 256>>>(q_w, k_w, out_w, wih, c1_w, c2_w);
    proj_kernel<<<264, 256>>>(tsteps, lin_w, lin_b, per_w, per_b,
                              q_b, q_g, q_be, k_b, k_g, k_be);
    attn_kernel<<<128, 256>>>(input, mask);
    out_gi_kernel<<<128, 384>>>(attn_g, attn_b, out_b, out_g, out_be, bih);
    gru_cls_kernel<<<8, 384>>>(whh, bhh, c1_b, c2_b, c3_w, c3_b, out);
}

// round 13
// speedup vs baseline: 1.4461x; 1.0331x over previous
#include <cuda_runtime.h>
#include <math.h>

#define EPSLN 1e-5f

// ---------------- device scratch ----------------
__device__ float g_qwT[128 * 128];
__device__ float g_kwT[128 * 128];
__device__ float g_outwT[64 * 128];
__device__ float g_wihT[128 * 384];
__device__ float g_c1T[128 * 128];
__device__ float g_c2T[128 * 128];
__device__ float g_q[128 * 128];        // (NT, E)
__device__ float g_kT[8 * 128 * 512];   // (B, E, T)
__device__ float g_gi[128 * 8 * 384];   // (t, b, 3H)

typedef unsigned long long u64;

__device__ __forceinline__ float tanhfast(float x) {
    float y;
    asm("tanh.approx.f32 %0, %1;" : "=f"(y) : "f"(x));
    return y;
}
__device__ __forceinline__ float sigfast(float x) {
    return fmaf(0.5f, tanhfast(0.5f * x), 0.5f);
}
__device__ __forceinline__ u64 fma2(u64 a, u64 b, u64 c) {
    u64 d;
    asm("fma.rn.f32x2 %0, %1, %2, %3;" : "=l"(d) : "l"(a), "l"(b), "l"(c));
    return d;
}
__device__ __forceinline__ u64 add2(u64 a, u64 b) {
    u64 d;
    asm("add.rn.f32x2 %0, %1, %2;" : "=l"(d) : "l"(a), "l"(b));
    return d;
}
__device__ __forceinline__ u64 pack2(float lo, float hi) {
    u64 r;
    asm("mov.b64 %0, {%1,%2};" : "=l"(r) : "f"(lo), "f"(hi));
    return r;
}
__device__ __forceinline__ float2 unpack2(u64 v) {
    float2 f;
    asm("mov.b64 {%0,%1}, %2;" : "=f"(f.x), "=f"(f.y) : "l"(v));
    return f;
}

// ---------------- fused weight transpose ----------------
__global__ void tr_all_kernel(const float* __restrict__ qw, const float* __restrict__ kw,
                              const float* __restrict__ ow, const float* __restrict__ wih,
                              const float* __restrict__ c1, const float* __restrict__ c2) {
    int idx = blockIdx.x * 256 + threadIdx.x;
    if (idx < 16384) { g_qwT[(idx & 127) * 128 + (idx >> 7)] = qw[idx]; return; }
    idx -= 16384;
    if (idx < 16384) { g_kwT[(idx & 127) * 128 + (idx >> 7)] = kw[idx]; return; }
    idx -= 16384;
    if (idx < 8192)  { int r = idx >> 6, c = idx & 63; g_outwT[c * 128 + r] = ow[idx]; return; }
    idx -= 8192;
    if (idx < 49152) { int r = idx >> 7, c = idx & 127; g_wihT[c * 384 + r] = wih[idx]; return; }
    idx -= 49152;
    if (idx < 16384) { g_c1T[(idx & 127) * 128 + (idx >> 7)] = c1[idx]; return; }
    idx -= 16384;
    if (idx < 16384) { g_c2T[(idx & 127) * 128 + (idx >> 7)] = c2[idx]; return; }
}

// ---------------- proj: 16 rows per block, 256 threads, f32x2 ----------------
__global__ __launch_bounds__(256) void proj_kernel(
    const float* __restrict__ timesteps,
    const float* __restrict__ lin_w, const float* __restrict__ lin_b,
    const float* __restrict__ per_w, const float* __restrict__ per_b,
    const float* __restrict__ q_b, const float* __restrict__ q_g,
    const float* __restrict__ q_be,
    const float* __restrict__ k_b, const float* __restrict__ k_g,
    const float* __restrict__ k_be) {
    __shared__ float tv_s[16];
    __shared__ float emb_s[16 * 128];
    __shared__ u64 emb_p[1024];     // [rg2][r2(4)][i(128)] rows (r2, r2+4) packed
    __shared__ float acc_s[16 * 128];
    int tid = threadIdx.x;
    int is_key = (blockIdx.x >= 8);
    int row0 = blockIdx.x * 16;

    if (tid < 16) {
        int u = row0 + tid;
        tv_s[tid] = is_key ? timesteps[u - 128] : (float)u * (1.0f / 127.0f);
    }
    __syncthreads();

    float lw = lin_w[0], lb = lin_b[0];
    #pragma unroll
    for (int s = 0; s < 8; s++) {
        int li = tid + s * 256;
        int r16 = li >> 7, col = li & 127;
        float tv = tv_s[r16];
        float ev = (col == 0) ? fmaf(tv, lw, lb)
                              : __sinf(fmaf(tv, per_w[col - 1], per_b[col - 1]));
        emb_s[li] = ev;
    }
    __syncthreads();

    #pragma unroll
    for (int s = 0; s < 4; s++) {
        int idx = tid + s * 256;
        int rg = idx >> 9, rem = idx & 511, r2 = rem >> 7, i = rem & 127;
        emb_p[idx] = pack2(emb_s[(rg * 8 + r2) * 128 + i],
                           emb_s[(rg * 8 + r2 + 4) * 128 + i]);
    }
    __syncthreads();

    const float* wT   = is_key ? g_kwT : g_qwT;
    const float* bias = is_key ? k_b : q_b;
    int rg = tid >> 7, ltid = tid & 127;
    float bv = bias[ltid];
    u64 acc2[4];
    #pragma unroll
    for (int r2 = 0; r2 < 4; r2++) acc2[r2] = pack2(bv, bv);
    const u64* ep = emb_p + rg * 512;
    #pragma unroll 8
    for (int i = 0; i < 128; i++) {
        float wv = wT[i * 128 + ltid];
        u64 w2 = pack2(wv, wv);
        #pragma unroll
        for (int r2 = 0; r2 < 4; r2++) acc2[r2] = fma2(ep[r2 * 128 + i], w2, acc2[r2]);
    }
    #pragma unroll
    for (int r2 = 0; r2 < 4; r2++) {
        float2 f = unpack2(acc2[r2]);
        acc_s[(rg * 8 + r2) * 128 + ltid]     = f.x;
        acc_s[(rg * 8 + r2 + 4) * 128 + ltid] = f.y;
    }
    __syncthreads();

    int warp = tid >> 5, lane = tid & 31;
    if (warp < 8) {
        const float* gg = is_key ? k_g : q_g;
        const float* bb = is_key ? k_be : q_be;
        #pragma unroll
        for (int rr = 0; rr < 2; rr++) {
            int r16 = warp + rr * 8;
            const float* arow = acc_s + r16 * 128;
            float v[4], s = 0.f, sq = 0.f;
            #pragma unroll
            for (int k = 0; k < 4; k++) {
                v[k] = arow[lane + 32 * k];
                s += v[k];
                sq = fmaf(v[k], v[k], sq);
            }
            #pragma unroll
            for (int o = 16; o > 0; o >>= 1) {
                s  += __shfl_xor_sync(0xffffffffu, s, o);
                sq += __shfl_xor_sync(0xffffffffu, sq, o);
            }
            float mean = s * (1.0f / 128.0f);
            float var = sq * (1.0f / 128.0f) - mean * mean;
            float rs = rsqrtf(var + EPSLN);
            int u = row0 + r16;
            #pragma unroll
            for (int k = 0; k < 4; k++) {
                int col = lane + 32 * k;
                float y = fmaf((v[k] - mean) * rs, gg[col], bb[col]);
                if (is_key) {
                    int idx = u - 128;
                    int b = idx >> 9, t = idx & 511;
                    g_kT[b * 65536 + col * 512 + t] = y;
                } else {
                    g_q[u * 128 + col] = y;
                }
            }
        }
    }
}

// ---------------- FUSED: scores + softmax + masked attention + LN + out + gi GEMM ----------------
// block = (b, qg): 8 query rows end-to-end. 384 threads.
__global__ __launch_bounds__(384) void attn_gi_kernel(
    const float* __restrict__ input, const float* __restrict__ mask,
    const float* __restrict__ attn_g, const float* __restrict__ attn_b,
    const float* __restrict__ out_b, const float* __restrict__ out_g,
    const float* __restrict__ out_be, const float* __restrict__ gru_bih) {
    __shared__ __align__(16) char sbuf[33024];
    u64*   q_p   = reinterpret_cast<u64*>(sbuf);            // [1024] phase A
    u64*   o_p   = reinterpret_cast<u64*>(sbuf);            // [512]  phase D (q_p dead)
    float* e_s   = reinterpret_cast<float*>(sbuf + 8192);   // [4096] phase A,B
    float* w_s   = reinterpret_cast<float*>(sbuf + 8192);   // [3072] phase D (e_s dead)
    float* att_s = reinterpret_cast<float*>(sbuf + 24576);  // [512]
    float* x2_s  = reinterpret_cast<float*>(sbuf + 26624);  // [512]
    float* o_s   = reinterpret_cast<float*>(sbuf + 28672);  // [1024]
    float* wred  = reinterpret_cast<float*>(sbuf + 32768);  // [64]

    int tid = threadIdx.x;
    int warp = tid >> 5, lane = tid & 31;
    int b = blockIdx.x >> 4;
    int qg = blockIdx.x & 15;

    // ---- phase A: scores + softmax (warps 0..7) ----
    for (int idx = tid; idx < 1024; idx += 384) {
        float v = g_q[qg * 1024 + idx];
        q_p[idx] = pack2(v, v);
    }
    __syncthreads();

    u64 acc2[8];
    if (tid < 256) {
        #pragma unroll
        for (int j = 0; j < 8; j++) acc2[j] = 0ull;
        const u64* kTb = reinterpret_cast<const u64*>(g_kT + b * 65536);
        #pragma unroll 8
        for (int e = 0; e < 128; e++) {
            u64 kv = kTb[e * 256 + tid];
            #pragma unroll
            for (int j = 0; j < 8; j++)
                acc2[j] = fma2(q_p[j * 128 + e], kv, acc2[j]);
        }
        #pragma unroll
        for (int j = 0; j < 8; j++) {
            float2 a = unpack2(acc2[j]);
            float m = fmaxf(a.x, a.y);
            #pragma unroll
            for (int o = 16; o > 0; o >>= 1) m = fmaxf(m, __shfl_xor_sync(0xffffffffu, m, o));
            if (lane == 0) wred[j * 8 + warp] = m;
        }
    }
    __syncthreads();
    if (tid < 256) {
        const float scale = 0.08838834764831845f; // 1/sqrt(128)
        int t0 = tid * 2;
        #pragma unroll
        for (int j = 0; j < 8; j++) {
            float M = wred[j * 8];
            #pragma unroll
            for (int w = 1; w < 8; w++) M = fmaxf(M, wred[j * 8 + w]);
            float2 a = unpack2(acc2[j]);
            e_s[j * 512 + t0]     = __expf((a.x - M) * scale);
            e_s[j * 512 + t0 + 1] = __expf((a.y - M) * scale);
        }
    }
    __syncthreads();

    // ---- phase B: per-channel masked weighted sum (all 12 warps) ----
    for (int c = warp; c < 32; c += 12) {
        const float* mrow = mask + (b * 32 + c) * 512;
        const float* irow = input + (b * 32 + c) * 512;
        float mv[16], miv[16];
        #pragma unroll
        for (int s = 0; s < 16; s++) {
            int t = lane + s * 32;
            float m = 1.0f - mrow[t];
            mv[s] = m;
            miv[s] = m * irow[t];
        }
        #pragma unroll
        for (int j = 0; j < 8; j++) {
            const float* erow = e_s + j * 512 + lane;
            float num = 0.f, den = 0.f;
            #pragma unroll
            for (int s = 0; s < 16; s++) {
                float e = erow[s * 32];
                num = fmaf(e, miv[s], num);
                den = fmaf(e, mv[s], den);
            }
            #pragma unroll
            for (int o = 16; o > 0; o >>= 1) {
                num += __shfl_down_sync(0xffffffffu, num, o);
                den += __shfl_down_sync(0xffffffffu, den, o);
            }
            if (lane == 0) {
                att_s[j * 64 + c]      = den > 0.f ? num / den : 0.f;
                att_s[j * 64 + 32 + c] = den > 0.f ? 1.f : 0.f;
            }
        }
    }
    __syncthreads();

    // ---- phase C: LN(64) -> out linear + LN (warps 0..7, row = warp) ----
    if (warp < 8) {
        const float2* arow = reinterpret_cast<const float2*>(att_s + warp * 64);
        float2 v = arow[lane];
        float s = v.x + v.y;
        float sq = fmaf(v.x, v.x, v.y * v.y);
        #pragma unroll
        for (int o = 16; o > 0; o >>= 1) {
            s  += __shfl_xor_sync(0xffffffffu, s, o);
            sq += __shfl_xor_sync(0xffffffffu, sq, o);
        }
        float mean = s * (1.0f / 64.0f);
        float var = sq * (1.0f / 64.0f) - mean * mean;
        float rs = rsqrtf(var + EPSLN);
        x2_s[warp * 64 + lane * 2]     = fmaf((v.x - mean) * rs, attn_g[lane * 2], attn_b[lane * 2]);
        x2_s[warp * 64 + lane * 2 + 1] = fmaf((v.y - mean) * rs, attn_g[lane * 2 + 1], attn_b[lane * 2 + 1]);
        __syncwarp();

        float acc[4], s2 = 0.f, sq2 = 0.f;
        #pragma unroll
        for (int k = 0; k < 4; k++) acc[k] = out_b[lane + 32 * k];
        const float* x2r = x2_s + warp * 64;
        #pragma unroll 8
        for (int i = 0; i < 64; i++) {
            float x = x2r[i];
            #pragma unroll
            for (int k = 0; k < 4; k++)
                acc[k] = fmaf(x, g_outwT[i * 128 + lane + 32 * k], acc[k]);
        }
        #pragma unroll
        for (int k = 0; k < 4; k++) { s2 += acc[k]; sq2 = fmaf(acc[k], acc[k], sq2); }
        #pragma unroll
        for (int o = 16; o > 0; o >>= 1) {
            s2  += __shfl_xor_sync(0xffffffffu, s2, o);
            sq2 += __shfl_xor_sync(0xffffffffu, sq2, o);
        }
        float mean2 = s2 * (1.0f / 128.0f);
        float var2 = sq2 * (1.0f / 128.0f) - mean2 * mean2;
        float rs2 = rsqrtf(var2 + EPSLN);
        #pragma unroll
        for (int k = 0; k < 4; k++) {
            int col = lane + 32 * k;
            o_s[warp * 128 + col] = fmaf((acc[k] - mean2) * rs2, out_g[col], out_be[col]);
        }
    }
    __syncthreads();

    // pack o rows (r2, r2+4)
    for (int idx = tid; idx < 512; idx += 384) {
        int r2 = idx >> 7, i = idx & 127;
        o_p[idx] = pack2(o_s[r2 * 128 + i], o_s[(r2 + 4) * 128 + i]);
    }

    // ---- phase D: gi GEMM, smem-tiled weights, f32x2 ----
    u64 accg[4];
    float bv = gru_bih[tid];
    #pragma unroll
    for (int r2 = 0; r2 < 4; r2++) accg[r2] = pack2(bv, bv);
    #pragma unroll 1
    for (int tile = 0; tile < 16; tile++) {
        __syncthreads();
        const float4* src = reinterpret_cast<const float4*>(g_wihT + tile * 8 * 384);
        float4* dst = reinterpret_cast<float4*>(w_s);
        dst[tid] = src[tid];
        dst[tid + 384] = src[tid + 384];
        __syncthreads();
        #pragma unroll
        for (int i = 0; i < 8; i++) {
            float wv = w_s[i * 384 + tid];
            u64 w2 = pack2(wv, wv);
            int ii = tile * 8 + i;
            #pragma unroll
            for (int r2 = 0; r2 < 4; r2++)
                accg[r2] = fma2(o_p[r2 * 128 + ii], w2, accg[r2]);
        }
    }
    #pragma unroll
    for (int r2 = 0; r2 < 4; r2++) {
        float2 f = unpack2(accg[r2]);
        int ntA = qg * 8 + r2, ntB = qg * 8 + r2 + 4;
        g_gi[(ntA * 8 + b) * 384 + tid] = f.x;
        g_gi[(ntB * 8 + b) * 384 + tid] = f.y;
    }
}

// ---------------- GRU (f32x2, 8 short chains, gi prefetch) + classifier ----------------
__global__ __launch_bounds__(384, 1) void gru_cls_kernel(
    const float* __restrict__ whh, const float* __restrict__ bhh,
    const float* __restrict__ c1b, const float* __restrict__ c2b,
    const float* __restrict__ c3w, const float* __restrict__ c3b,
    float* __restrict__ out) {
    __shared__ __align__(16) float h_s[128];
    __shared__ float r_s[128], z_s[128], hn_s[128], gin_s[128];
    int tid = threadIdx.x;
    int b = blockIdx.x;

    u64 wp[64];
    const u64* wrow = reinterpret_cast<const u64*>(whh + tid * 128);
    #pragma unroll
    for (int i = 0; i < 64; i++) wp[i] = wrow[i];
    float bh = bhh[tid];
    if (tid < 128) h_s[tid] = 0.f;

    const float* gptr = g_gi + b * 384 + tid;
    int g = tid >> 7, j = tid & 127;
    float giv = gptr[0];

    for (int t = 0; t < 128; t++) {
        __syncthreads();
        float giv_next = (t < 127) ? gptr[(t + 1) * 3072] : 0.f;
        u64 a2[8];
        #pragma unroll
        for (int k = 0; k < 8; k++) a2[k] = 0ull;
        const ulonglong2* h2 = reinterpret_cast<const ulonglong2*>(h_s);
        #pragma unroll
        for (int i = 0; i < 32; i += 4) {
            ulonglong2 hv0 = h2[i], hv1 = h2[i + 1], hv2 = h2[i + 2], hv3 = h2[i + 3];
            a2[0] = fma2(wp[2 * i],     hv0.x, a2[0]);
            a2[1] = fma2(wp[2 * i + 1], hv0.y, a2[1]);
            a2[2] = fma2(wp[2 * i + 2], hv1.x, a2[2]);
            a2[3] = fma2(wp[2 * i + 3], hv1.y, a2[3]);
            a2[4] = fma2(wp[2 * i + 4], hv2.x, a2[4]);
            a2[5] = fma2(wp[2 * i + 5], hv2.y, a2[5]);
            a2[6] = fma2(wp[2 * i + 6], hv3.x, a2[6]);
            a2[7] = fma2(wp[2 * i + 7], hv3.y, a2[7]);
        }
        a2[0] = add2(a2[0], a2[1]);
        a2[2] = add2(a2[2], a2[3]);
        a2[4] = add2(a2[4], a2[5]);
        a2[6] = add2(a2[6], a2[7]);
        a2[0] = add2(a2[0], a2[2]);
        a2[4] = add2(a2[4], a2[6]);
        a2[0] = add2(a2[0], a2[4]);
        float2 f = unpack2(a2[0]);
        float accv = f.x + f.y + bh;
        if (g == 0)      r_s[j] = accv + giv;
        else if (g == 1) z_s[j] = accv + giv;
        else           { hn_s[j] = accv; gin_s[j] = giv; }
        __syncthreads();
        if (tid < 128) {
            float r = sigfast(r_s[tid]);
            float z = sigfast(z_s[tid]);
            float n = tanhfast(fmaf(r, hn_s[tid], gin_s[tid]));
            h_s[tid] = fmaf(z, h_s[tid] - n, n);
        }
        giv = giv_next;
    }
    __syncthreads();

    if (tid < 128) {
        float a = c1b[tid];
        #pragma unroll 8
        for (int i = 0; i < 128; i++) a = fmaf(h_s[i], g_c1T[i * 128 + tid], a);
        r_s[tid] = fmaxf(a, 0.f);
    }
    __syncthreads();
    if (tid < 128) {
        float a2v = c2b[tid];
        #pragma unroll 8
        for (int i = 0; i < 128; i++) a2v = fmaf(r_s[i], g_c2T[i * 128 + tid], a2v);
        z_s[tid] = fmaxf(a2v, 0.f);
    }
    __syncthreads();
    if (tid < 2) {
        float a3 = c3b[tid];
        #pragma unroll 8
        for (int i = 0; i < 128; i++) a3 = fmaf(z_s[i], c3w[tid * 128 + i], a3);
        out[b * 2 + tid] = a3;
    }
}

// ---------------- launch ----------------
extern "C" void kernel_launch(void* const* d_in, const int* in_sizes, int n_in,
                              void* d_out, int out_size) {
    const float* input  = (const float*)d_in[0];
    const float* mask   = (const float*)d_in[1];
    const float* tsteps = (const float*)d_in[2];
    const float* per_w  = (const float*)d_in[3];
    const float* per_b  = (const float*)d_in[4];
    const float* lin_w  = (const float*)d_in[5];
    const float* lin_b  = (const float*)d_in[6];
    const float* q_w    = (const float*)d_in[7];
    const float* q_b    = (const float*)d_in[8];
    const float* q_g    = (const float*)d_in[9];
    const float* q_be   = (const float*)d_in[10];
    const float* k_w    = (const float*)d_in[11];
    const float* k_b    = (const float*)d_in[12];
    const float* k_g    = (const float*)d_in[13];
    const float* k_be   = (const float*)d_in[14];
    const float* attn_g = (const float*)d_in[15];
    const float* attn_b = (const float*)d_in[16];
    const float* out_w  = (const float*)d_in[17];
    const float* out_b  = (const float*)d_in[18];
    const float* out_g  = (const float*)d_in[19];
    const float* out_be = (const float*)d_in[20];
    const float* wih    = (const float*)d_in[21];
    const float* whh    = (const float*)d_in[22];
    const float* bih    = (const float*)d_in[23];
    const float* bhh    = (const float*)d_in[24];
    const float* c1_w   = (const float*)d_in[25];
    const float* c1_b   = (const float*)d_in[26];
    const float* c2_w   = (const float*)d_in[27];
    const float* c2_b   = (const float*)d_in[28];
    const float* c3_w   = (const float*)d_in[29];
    const float* c3_b   = (const float*)d_in[30];
    float* out = (float*)d_out;

    tr_all_kernel<<<480, 256>>>(q_w, k_w, out_w, wih, c1_w, c2_w);
    proj_kernel<<<264, 256>>>(tsteps, lin_w, lin_b, per_w, per_b,
                              q_b, q_g, q_be, k_b, k_g, k_be);
    attn_gi_kernel<<<128, 384>>>(input, mask, attn_g, attn_b,
                                 out_b, out_g, out_be, bih);
    gru_cls_kernel<<<8, 384>>>(whh, bhh, c1_b, c2_b, c3_w, c3_b, out);
}